// round 1
// baseline (speedup 1.0000x reference)
#include <cuda_runtime.h>
#include <cstddef>

#define N_NODES 100000
#define N_EDGES 600000
#define HD 128
#define BM 64                       // rows per GEMM block
#define HS_STRIDE 132               // padded H-tile row stride (floats)
#define GEMM_SMEM_FLOATS (HD*HD + BM*HS_STRIDE)
#define GEMM_SMEM_BYTES (GEMM_SMEM_FLOATS * 4)

// Scratch (allocation-free): transformed features, aggregation buffer, layer-1 output
__device__ float g_M[(size_t)N_NODES * HD];
__device__ float g_AGG[(size_t)N_NODES * HD];
__device__ float g_H[(size_t)N_NODES * HD];

// out[row, :] = (X[idx ? idx[row] : row, :] @ W) * norm[row]
__global__ void gemm_norm_kernel(const float* __restrict__ X,
                                 const int* __restrict__ idx,
                                 const float* __restrict__ W,
                                 const float* __restrict__ norm,
                                 float* __restrict__ out) {
    extern __shared__ float smem[];
    float* Ws = smem;                 // [128][128]
    float* Hs = smem + HD * HD;       // [BM][HS_STRIDE]

    const int t = threadIdx.x;        // 256 threads
    const int row0 = blockIdx.x * BM;

    // Load W (16384 floats = 4096 float4) into smem
    {
        const float4* W4 = reinterpret_cast<const float4*>(W);
        float4* Ws4 = reinterpret_cast<float4*>(Ws);
        #pragma unroll
        for (int i = 0; i < 16; ++i)
            Ws4[i * 256 + t] = W4[i * 256 + t];
    }
    // Load H tile (BM rows x 128 cols, gathered through idx for layer 1)
    for (int i = t; i < BM * (HD / 4); i += 256) {
        int r = i >> 5;               // local row
        int c = i & 31;               // float4 col
        int row = row0 + r;
        float4 v = make_float4(0.f, 0.f, 0.f, 0.f);
        if (row < N_NODES) {
            int srow = idx ? idx[row] : row;
            v = reinterpret_cast<const float4*>(X + (size_t)srow * HD)[c];
        }
        reinterpret_cast<float4*>(Hs + r * HS_STRIDE)[c] = v;
    }
    __syncthreads();

    const int tx = t & 15;            // cols: tx*4..+3 and 64+tx*4..+3
    const int ty = t >> 4;            // rows: ty*4..+3

    float acc[4][8];
    #pragma unroll
    for (int i = 0; i < 4; ++i)
        #pragma unroll
        for (int j = 0; j < 8; ++j) acc[i][j] = 0.f;

    #pragma unroll 4
    for (int k = 0; k < HD; ++k) {
        const float4 wA = *reinterpret_cast<const float4*>(Ws + k * HD + tx * 4);
        const float4 wB = *reinterpret_cast<const float4*>(Ws + k * HD + tx * 4 + 64);
        #pragma unroll
        for (int i = 0; i < 4; ++i) {
            const float h = Hs[(ty * 4 + i) * HS_STRIDE + k];
            acc[i][0] += h * wA.x; acc[i][1] += h * wA.y;
            acc[i][2] += h * wA.z; acc[i][3] += h * wA.w;
            acc[i][4] += h * wB.x; acc[i][5] += h * wB.y;
            acc[i][6] += h * wB.z; acc[i][7] += h * wB.w;
        }
    }

    #pragma unroll
    for (int i = 0; i < 4; ++i) {
        int row = row0 + ty * 4 + i;
        if (row < N_NODES) {
            float s = norm[row];
            float4 oA = make_float4(acc[i][0] * s, acc[i][1] * s, acc[i][2] * s, acc[i][3] * s);
            float4 oB = make_float4(acc[i][4] * s, acc[i][5] * s, acc[i][6] * s, acc[i][7] * s);
            reinterpret_cast<float4*>(out + (size_t)row * HD + tx * 4)[0] = oA;
            reinterpret_cast<float4*>(out + (size_t)row * HD + 64 + tx * 4)[0] = oB;
        }
    }
}

// AGG[dst[e], :] += M[src[e], :]   (one warp per edge, float4 per lane, 4 REDs)
__global__ void scatter_kernel(const float* __restrict__ M,
                               const int* __restrict__ src,
                               const int* __restrict__ dst,
                               float* __restrict__ AGG) {
    const int e = blockIdx.x * 8 + (threadIdx.x >> 5);
    const int lane = threadIdx.x & 31;
    if (e >= N_EDGES) return;
    const int s = src[e];
    const int d = dst[e];
    const float4 v = reinterpret_cast<const float4*>(M + (size_t)s * HD)[lane];
    float* a = AGG + (size_t)d * HD + lane * 4;
    atomicAdd(a + 0, v.x);
    atomicAdd(a + 1, v.y);
    atomicAdd(a + 2, v.z);
    atomicAdd(a + 3, v.w);
}

// out = leaky_relu(AGG * norm + b, 0.2)
__global__ void epi_kernel(const float* __restrict__ AGG,
                           const float* __restrict__ norm,
                           const float* __restrict__ b,
                           float* __restrict__ out) {
    const size_t i = (size_t)blockIdx.x * blockDim.x + threadIdx.x;  // float4 index
    const size_t total = (size_t)N_NODES * (HD / 4);
    if (i >= total) return;
    const int row = (int)(i >> 5);
    const int c4 = (int)(i & 31);
    const float s = norm[row];
    const float4 a = reinterpret_cast<const float4*>(AGG)[i];
    const float4 bb = reinterpret_cast<const float4*>(b)[c4];
    float4 n;
    n.x = a.x * s + bb.x;
    n.y = a.y * s + bb.y;
    n.z = a.z * s + bb.z;
    n.w = a.w * s + bb.w;
    n.x = n.x > 0.f ? n.x : 0.2f * n.x;
    n.y = n.y > 0.f ? n.y : 0.2f * n.y;
    n.z = n.z > 0.f ? n.z : 0.2f * n.z;
    n.w = n.w > 0.f ? n.w : 0.2f * n.w;
    reinterpret_cast<float4*>(out)[i] = n;
}

extern "C" void kernel_launch(void* const* d_in, const int* in_sizes, int n_in,
                              void* d_out, int out_size) {
    const int*   node_id = (const int*)d_in[0];
    const int*   src     = (const int*)d_in[1];
    const int*   dst     = (const int*)d_in[2];
    const float* norm    = (const float*)d_in[3];
    const float* embed   = (const float*)d_in[4];
    const float* W1      = (const float*)d_in[5];
    const float* b1      = (const float*)d_in[6];
    const float* W2      = (const float*)d_in[7];
    const float* b2      = (const float*)d_in[8];
    float* out = (float*)d_out;

    void *pM, *pA, *pH;
    cudaGetSymbolAddress(&pM, g_M);
    cudaGetSymbolAddress(&pA, g_AGG);
    cudaGetSymbolAddress(&pH, g_H);
    float* M   = (float*)pM;
    float* AGG = (float*)pA;
    float* H   = (float*)pH;

    cudaFuncSetAttribute(gemm_norm_kernel,
                         cudaFuncAttributeMaxDynamicSharedMemorySize,
                         GEMM_SMEM_BYTES);

    const int gemm_grid    = (N_NODES + BM - 1) / BM;       // 1563
    const int scatter_grid = (N_EDGES + 7) / 8;             // 75000
    const int epi_grid     = (N_NODES * (HD / 4) + 255) / 256;  // 12500
    const size_t agg_bytes = (size_t)N_NODES * HD * sizeof(float);

    // ---- Layer 1 (gather fused into GEMM A-load) ----
    gemm_norm_kernel<<<gemm_grid, 256, GEMM_SMEM_BYTES>>>(embed, node_id, W1, norm, M);
    cudaMemsetAsync(AGG, 0, agg_bytes);
    scatter_kernel<<<scatter_grid, 256>>>(M, src, dst, AGG);
    epi_kernel<<<epi_grid, 256>>>(AGG, norm, b1, H);

    // ---- Layer 2 ----
    gemm_norm_kernel<<<gemm_grid, 256, GEMM_SMEM_BYTES>>>(H, nullptr, W2, norm, M);
    cudaMemsetAsync(AGG, 0, agg_bytes);
    scatter_kernel<<<scatter_grid, 256>>>(M, src, dst, AGG);
    epi_kernel<<<epi_grid, 256>>>(AGG, norm, b2, out);
}

// round 2
// speedup vs baseline: 1.6046x; 1.6046x over previous
#include <cuda_runtime.h>
#include <cstddef>

#define N_NODES 100000
#define N_EDGES 600000
#define HD 128
#define BM 64                       // rows per GEMM block
#define HS_STRIDE 132               // padded H-tile row stride (floats)
#define GEMM_SMEM_FLOATS (HD*HD + BM*HS_STRIDE)
#define GEMM_SMEM_BYTES (GEMM_SMEM_FLOATS * 4)

typedef unsigned long long u64;

// Scratch (allocation-free)
__device__ float g_M[(size_t)N_NODES * HD];
__device__ float g_AGG[(size_t)N_NODES * HD];

// ---- packed f32x2 helpers (sm_103a) ----
__device__ __forceinline__ void ffma2(u64& d, u64 a, u64 b) {
    asm("fma.rn.f32x2 %0, %1, %2, %0;" : "+l"(d) : "l"(a), "l"(b));
}
__device__ __forceinline__ u64 pack2(float x, float y) {
    u64 r; asm("mov.b64 %0, {%1, %2};" : "=l"(r) : "f"(x), "f"(y)); return r;
}
__device__ __forceinline__ u64 mul2(u64 a, u64 b) {
    u64 r; asm("mul.rn.f32x2 %0, %1, %2;" : "=l"(r) : "l"(a), "l"(b)); return r;
}

__device__ __forceinline__ float leaky(float x) { return x > 0.f ? x : 0.2f * x; }

// out[row,:] = (A[row,:] @ W) * norm[row]
// A[row,:] = X[idx[row],:]                         (gather mode, idx != null)
//          = leaky(X[row,:] * norm[row] + bias[:]) (transform mode, bias != null)
//          = X[row,:]                              (plain)
__global__ void gemm_norm_kernel(const float* __restrict__ X,
                                 const int* __restrict__ idx,
                                 const float* __restrict__ W,
                                 const float* __restrict__ bias,
                                 const float* __restrict__ norm,
                                 float* __restrict__ out) {
    extern __shared__ float smem[];
    float* Ws = smem;                 // [128][128]
    float* Hs = smem + HD * HD;       // [BM][HS_STRIDE]

    const int t = threadIdx.x;        // 256 threads
    const int row0 = blockIdx.x * BM;

    // Load W into smem (4096 float4)
    {
        const float4* W4 = reinterpret_cast<const float4*>(W);
        float4* Ws4 = reinterpret_cast<float4*>(Ws);
        #pragma unroll
        for (int i = 0; i < 16; ++i)
            Ws4[i * 256 + t] = W4[i * 256 + t];
    }
    // Stage A tile (fused gather / fused previous-layer epilogue)
    for (int i = t; i < BM * (HD / 4); i += 256) {
        int r = i >> 5;               // local row
        int c = i & 31;               // float4 col
        int row = row0 + r;
        float4 v = make_float4(0.f, 0.f, 0.f, 0.f);
        if (row < N_NODES) {
            if (idx) {
                int srow = idx[row];
                v = reinterpret_cast<const float4*>(X + (size_t)srow * HD)[c];
            } else {
                v = reinterpret_cast<const float4*>(X + (size_t)row * HD)[c];
                if (bias) {
                    float s = __ldg(norm + row);
                    float4 bb = __ldg(reinterpret_cast<const float4*>(bias) + c);
                    v.x = leaky(v.x * s + bb.x);
                    v.y = leaky(v.y * s + bb.y);
                    v.z = leaky(v.z * s + bb.z);
                    v.w = leaky(v.w * s + bb.w);
                }
            }
        }
        reinterpret_cast<float4*>(Hs + r * HS_STRIDE)[c] = v;
    }
    __syncthreads();

    const int tx = t & 15;            // col pairs at tx*4 and 64+tx*4
    const int ty = t >> 4;            // rows ty*4 .. ty*4+3

    u64 acc[4][4];                    // [row][colpair]: {tx*4+0/1, tx*4+2/3, 64+tx*4+0/1, 64+tx*4+2/3}
    #pragma unroll
    for (int i = 0; i < 4; ++i)
        #pragma unroll
        for (int j = 0; j < 4; ++j) acc[i][j] = 0ull;

    const float* HsBase = Hs + (ty * 4) * HS_STRIDE;
    const float* WsBase = Ws + tx * 4;

    #pragma unroll 2
    for (int kk = 0; kk < HD / 4; ++kk) {
        float4 h[4];
        #pragma unroll
        for (int i = 0; i < 4; ++i)
            h[i] = *reinterpret_cast<const float4*>(HsBase + i * HS_STRIDE + kk * 4);
        #pragma unroll
        for (int q = 0; q < 4; ++q) {
            const int k = kk * 4 + q;
            const ulonglong2 wA = *reinterpret_cast<const ulonglong2*>(WsBase + k * HD);
            const ulonglong2 wB = *reinterpret_cast<const ulonglong2*>(WsBase + k * HD + 64);
            #pragma unroll
            for (int i = 0; i < 4; ++i) {
                const float hv = (q == 0) ? h[i].x : (q == 1) ? h[i].y : (q == 2) ? h[i].z : h[i].w;
                const u64 hh = pack2(hv, hv);
                ffma2(acc[i][0], hh, wA.x);
                ffma2(acc[i][1], hh, wA.y);
                ffma2(acc[i][2], hh, wB.x);
                ffma2(acc[i][3], hh, wB.y);
            }
        }
    }

    #pragma unroll
    for (int i = 0; i < 4; ++i) {
        int row = row0 + ty * 4 + i;
        if (row < N_NODES) {
            float s = norm[row];
            u64 ss = pack2(s, s);
            ulonglong2 oA, oB;
            oA.x = mul2(acc[i][0], ss); oA.y = mul2(acc[i][1], ss);
            oB.x = mul2(acc[i][2], ss); oB.y = mul2(acc[i][3], ss);
            *reinterpret_cast<ulonglong2*>(out + (size_t)row * HD + tx * 4) = oA;
            *reinterpret_cast<ulonglong2*>(out + (size_t)row * HD + 64 + tx * 4) = oB;
        }
    }
}

// AGG[dst[e], :] += M[src[e], :]   (warp per edge, one 16B vector RED per lane)
__global__ void scatter_kernel(const float* __restrict__ M,
                               const int* __restrict__ src,
                               const int* __restrict__ dst,
                               float* __restrict__ AGG) {
    const int e = blockIdx.x * 8 + (threadIdx.x >> 5);
    const int lane = threadIdx.x & 31;
    if (e >= N_EDGES) return;
    const int s = __ldg(src + e);
    const int d = __ldg(dst + e);
    const float4 v = reinterpret_cast<const float4*>(M + (size_t)s * HD)[lane];
    float* a = AGG + (size_t)d * HD + lane * 4;
    asm volatile("red.global.add.v4.f32 [%0], {%1, %2, %3, %4};"
                 :: "l"(a), "f"(v.x), "f"(v.y), "f"(v.z), "f"(v.w)
                 : "memory");
}

// out = leaky(AGG * norm + b)  (final layer only)
__global__ void epi_kernel(const float* __restrict__ AGG,
                           const float* __restrict__ norm,
                           const float* __restrict__ b,
                           float* __restrict__ out) {
    const size_t i = (size_t)blockIdx.x * blockDim.x + threadIdx.x;  // float4 index
    if (i >= (size_t)N_NODES * (HD / 4)) return;
    const int row = (int)(i >> 5);
    const int c4 = (int)(i & 31);
    const float s = __ldg(norm + row);
    const float4 a = reinterpret_cast<const float4*>(AGG)[i];
    const float4 bb = __ldg(reinterpret_cast<const float4*>(b) + c4);
    float4 n;
    n.x = leaky(a.x * s + bb.x);
    n.y = leaky(a.y * s + bb.y);
    n.z = leaky(a.z * s + bb.z);
    n.w = leaky(a.w * s + bb.w);
    reinterpret_cast<float4*>(out)[i] = n;
}

extern "C" void kernel_launch(void* const* d_in, const int* in_sizes, int n_in,
                              void* d_out, int out_size) {
    const int*   node_id = (const int*)d_in[0];
    const int*   src     = (const int*)d_in[1];
    const int*   dst     = (const int*)d_in[2];
    const float* norm    = (const float*)d_in[3];
    const float* embed   = (const float*)d_in[4];
    const float* W1      = (const float*)d_in[5];
    const float* b1      = (const float*)d_in[6];
    const float* W2      = (const float*)d_in[7];
    const float* b2      = (const float*)d_in[8];
    float* out = (float*)d_out;

    void *pM, *pA;
    cudaGetSymbolAddress(&pM, g_M);
    cudaGetSymbolAddress(&pA, g_AGG);
    float* M   = (float*)pM;
    float* AGG = (float*)pA;

    cudaFuncSetAttribute(gemm_norm_kernel,
                         cudaFuncAttributeMaxDynamicSharedMemorySize,
                         GEMM_SMEM_BYTES);

    const int gemm_grid    = (N_NODES + BM - 1) / BM;             // 1563
    const int scatter_grid = (N_EDGES + 7) / 8;                   // 75000
    const int epi_grid     = (N_NODES * (HD / 4) + 255) / 256;    // 12500
    const size_t agg_bytes = (size_t)N_NODES * HD * sizeof(float);

    // ---- Layer 1 (embedding gather fused into GEMM A-load) ----
    gemm_norm_kernel<<<gemm_grid, 256, GEMM_SMEM_BYTES>>>(embed, node_id, W1, nullptr, norm, M);
    cudaMemsetAsync(AGG, 0, agg_bytes);
    scatter_kernel<<<scatter_grid, 256>>>(M, src, dst, AGG);

    // ---- Layer 2 (layer-1 epilogue fused into GEMM A-load) ----
    gemm_norm_kernel<<<gemm_grid, 256, GEMM_SMEM_BYTES>>>(AGG, nullptr, W2, b1, norm, M);
    cudaMemsetAsync(AGG, 0, agg_bytes);
    scatter_kernel<<<scatter_grid, 256>>>(M, src, dst, AGG);
    epi_kernel<<<epi_grid, 256>>>(AGG, norm, b2, out);
}

// round 3
// speedup vs baseline: 2.0484x; 1.2766x over previous
#include <cuda_runtime.h>
#include <cstddef>

#define N_NODES 100000
#define N_EDGES 600000
#define HD 128
#define BM 64
#define HS_STRIDE 132
#define GEMM_SMEM_FLOATS (HD*HD + BM*HS_STRIDE)
#define GEMM_SMEM_BYTES (GEMM_SMEM_FLOATS * 4)
#define SCAN_CHUNK 1024
#define NBLK ((N_NODES + SCAN_CHUNK - 1) / SCAN_CHUNK)   // 98

typedef unsigned long long u64;

// Scratch (allocation-free, __device__ globals)
__device__ float g_M[(size_t)N_NODES * HD];
__device__ float g_H[(size_t)N_NODES * HD];
__device__ int   g_deg[N_NODES];
__device__ int   g_rowptr[N_NODES];
__device__ int   g_cursor[N_NODES];
__device__ int   g_ssrc[N_EDGES];
__device__ int   g_partials[NBLK];

// ---- packed f32x2 helpers (sm_103a) ----
__device__ __forceinline__ void ffma2(u64& d, u64 a, u64 b) {
    asm("fma.rn.f32x2 %0, %1, %2, %0;" : "+l"(d) : "l"(a), "l"(b));
}
__device__ __forceinline__ u64 pack2(float x, float y) {
    u64 r; asm("mov.b64 %0, {%1, %2};" : "=l"(r) : "f"(x), "f"(y)); return r;
}
__device__ __forceinline__ u64 mul2(u64 a, u64 b) {
    u64 r; asm("mul.rn.f32x2 %0, %1, %2;" : "=l"(r) : "l"(a), "l"(b)); return r;
}
__device__ __forceinline__ float leaky(float x) { return x > 0.f ? x : 0.2f * x; }

// ================= CSR build =================

__global__ void hist_kernel(const int* __restrict__ dst, int* __restrict__ deg) {
    int e = blockIdx.x * 256 + threadIdx.x;
    if (e < N_EDGES) atomicAdd(&deg[dst[e]], 1);
}

// Per-block exclusive scan of deg (chunk of 1024) -> rowptr (local), block totals -> partials
__global__ void scan_block_kernel(const int* __restrict__ deg,
                                  int* __restrict__ rowptr,
                                  int* __restrict__ partials) {
    __shared__ int wsum[8];
    const int t = threadIdx.x;          // 256
    const int base = blockIdx.x * SCAN_CHUNK + t * 4;
    int v[4];
    #pragma unroll
    for (int j = 0; j < 4; ++j) {
        int i = base + j;
        v[j] = (i < N_NODES) ? deg[i] : 0;
    }
    int s = v[0] + v[1] + v[2] + v[3];
    const int lane = t & 31, wid = t >> 5;
    int x = s;
    #pragma unroll
    for (int o = 1; o < 32; o <<= 1) {
        int y = __shfl_up_sync(~0u, x, o);
        if (lane >= o) x += y;
    }
    if (lane == 31) wsum[wid] = x;
    __syncthreads();
    if (wid == 0) {
        int ws = (lane < 8) ? wsum[lane] : 0;
        #pragma unroll
        for (int o = 1; o < 8; o <<= 1) {
            int y = __shfl_up_sync(~0u, ws, o);
            if (lane >= o) ws += y;
        }
        if (lane < 8) wsum[lane] = ws;   // inclusive warp totals
    }
    __syncthreads();
    int run = (x - s) + (wid > 0 ? wsum[wid - 1] : 0);  // exclusive prefix
    #pragma unroll
    for (int j = 0; j < 4; ++j) {
        int i = base + j;
        if (i < N_NODES) rowptr[i] = run;
        run += v[j];
    }
    if (t == 0) partials[blockIdx.x] = wsum[7];
}

// Single-block exclusive scan of partials (NBLK <= 128)
__global__ void scan_partials_kernel(int* __restrict__ partials) {
    __shared__ int wsum[4];
    const int t = threadIdx.x;          // 128
    int v = (t < NBLK) ? partials[t] : 0;
    const int lane = t & 31, wid = t >> 5;
    int x = v;
    #pragma unroll
    for (int o = 1; o < 32; o <<= 1) {
        int y = __shfl_up_sync(~0u, x, o);
        if (lane >= o) x += y;
    }
    if (lane == 31) wsum[wid] = x;
    __syncthreads();
    if (t == 0) {
        int a = 0;
        #pragma unroll
        for (int w = 0; w < 4; ++w) { int s2 = wsum[w]; wsum[w] = a; a += s2; }
    }
    __syncthreads();
    int excl = (x - v) + wsum[wid];
    if (t < NBLK) partials[t] = excl;
}

__global__ void scan_add_kernel(int* __restrict__ rowptr,
                                const int* __restrict__ partials,
                                int* __restrict__ cursor) {
    int i = blockIdx.x * 256 + threadIdx.x;
    if (i < N_NODES) {
        int r = rowptr[i] + partials[i >> 10];
        rowptr[i] = r;
        cursor[i] = r;
    }
}

__global__ void permute_kernel(const int* __restrict__ src,
                               const int* __restrict__ dst,
                               int* __restrict__ cursor,
                               int* __restrict__ ssrc) {
    int e = blockIdx.x * 256 + threadIdx.x;
    if (e < N_EDGES) {
        int d = dst[e];
        int pos = atomicAdd(&cursor[d], 1);
        ssrc[pos] = src[e];
    }
}

// ================= GEMM: out[row,:] = (X[gather(row),:] @ W) * norm[row] =================

__global__ void gemm_norm_kernel(const float* __restrict__ X,
                                 const int* __restrict__ idx,   // nullable
                                 const float* __restrict__ W,
                                 const float* __restrict__ norm,
                                 float* __restrict__ out) {
    extern __shared__ float smem[];
    float* Ws = smem;                 // [128][128]
    float* Hs = smem + HD * HD;       // [BM][HS_STRIDE]

    const int t = threadIdx.x;        // 256
    const int row0 = blockIdx.x * BM;

    {
        const float4* W4 = reinterpret_cast<const float4*>(W);
        float4* Ws4 = reinterpret_cast<float4*>(Ws);
        #pragma unroll
        for (int i = 0; i < 16; ++i)
            Ws4[i * 256 + t] = W4[i * 256 + t];
    }
    for (int i = t; i < BM * (HD / 4); i += 256) {
        int r = i >> 5;
        int c = i & 31;
        int row = row0 + r;
        float4 v = make_float4(0.f, 0.f, 0.f, 0.f);
        if (row < N_NODES) {
            int srow = idx ? idx[row] : row;
            v = reinterpret_cast<const float4*>(X + (size_t)srow * HD)[c];
        }
        reinterpret_cast<float4*>(Hs + r * HS_STRIDE)[c] = v;
    }
    __syncthreads();

    const int tx = t & 15;
    const int ty = t >> 4;

    u64 acc[4][4];
    #pragma unroll
    for (int i = 0; i < 4; ++i)
        #pragma unroll
        for (int j = 0; j < 4; ++j) acc[i][j] = 0ull;

    const float* HsBase = Hs + (ty * 4) * HS_STRIDE;
    const float* WsBase = Ws + tx * 4;

    #pragma unroll 2
    for (int kk = 0; kk < HD / 4; ++kk) {
        float4 h[4];
        #pragma unroll
        for (int i = 0; i < 4; ++i)
            h[i] = *reinterpret_cast<const float4*>(HsBase + i * HS_STRIDE + kk * 4);
        #pragma unroll
        for (int q = 0; q < 4; ++q) {
            const int k = kk * 4 + q;
            const ulonglong2 wA = *reinterpret_cast<const ulonglong2*>(WsBase + k * HD);
            const ulonglong2 wB = *reinterpret_cast<const ulonglong2*>(WsBase + k * HD + 64);
            #pragma unroll
            for (int i = 0; i < 4; ++i) {
                const float hv = (q == 0) ? h[i].x : (q == 1) ? h[i].y : (q == 2) ? h[i].z : h[i].w;
                const u64 hh = pack2(hv, hv);
                ffma2(acc[i][0], hh, wA.x);
                ffma2(acc[i][1], hh, wA.y);
                ffma2(acc[i][2], hh, wB.x);
                ffma2(acc[i][3], hh, wB.y);
            }
        }
    }

    #pragma unroll
    for (int i = 0; i < 4; ++i) {
        int row = row0 + ty * 4 + i;
        if (row < N_NODES) {
            float s = norm[row];
            u64 ss = pack2(s, s);
            ulonglong2 oA, oB;
            oA.x = mul2(acc[i][0], ss); oA.y = mul2(acc[i][1], ss);
            oB.x = mul2(acc[i][2], ss); oB.y = mul2(acc[i][3], ss);
            *reinterpret_cast<ulonglong2*>(out + (size_t)row * HD + tx * 4) = oA;
            *reinterpret_cast<ulonglong2*>(out + (size_t)row * HD + 64 + tx * 4) = oB;
        }
    }
}

// ================= Gather-aggregate + fused epilogue =================
// out[n,:] = leaky( (sum_{e: dst==n} M[src[e],:]) * norm[n] + b[:] )
__global__ void gather_kernel(const float* __restrict__ M,
                              const int* __restrict__ rowptr,
                              const int* __restrict__ deg,
                              const int* __restrict__ ssrc,
                              const float* __restrict__ norm,
                              const float* __restrict__ b,
                              float* __restrict__ out) {
    const int node = blockIdx.x * 8 + (threadIdx.x >> 5);
    const int lane = threadIdx.x & 31;
    if (node >= N_NODES) return;
    const int start = __ldg(rowptr + node);
    const int d = __ldg(deg + node);

    float4 acc = make_float4(0.f, 0.f, 0.f, 0.f);
    #pragma unroll 4
    for (int j = 0; j < d; ++j) {
        int s = __ldg(ssrc + start + j);
        float4 v = __ldg(reinterpret_cast<const float4*>(M + (size_t)s * HD) + lane);
        acc.x += v.x; acc.y += v.y; acc.z += v.z; acc.w += v.w;
    }
    const float sc = __ldg(norm + node);
    const float4 bb = __ldg(reinterpret_cast<const float4*>(b) + lane);
    float4 n;
    n.x = leaky(acc.x * sc + bb.x);
    n.y = leaky(acc.y * sc + bb.y);
    n.z = leaky(acc.z * sc + bb.z);
    n.w = leaky(acc.w * sc + bb.w);
    reinterpret_cast<float4*>(out + (size_t)node * HD)[lane] = n;
}

extern "C" void kernel_launch(void* const* d_in, const int* in_sizes, int n_in,
                              void* d_out, int out_size) {
    const int*   node_id = (const int*)d_in[0];
    const int*   src     = (const int*)d_in[1];
    const int*   dst     = (const int*)d_in[2];
    const float* norm    = (const float*)d_in[3];
    const float* embed   = (const float*)d_in[4];
    const float* W1      = (const float*)d_in[5];
    const float* b1      = (const float*)d_in[6];
    const float* W2      = (const float*)d_in[7];
    const float* b2      = (const float*)d_in[8];
    float* out = (float*)d_out;

    void *pM, *pH, *pDeg, *pRow, *pCur, *pSS, *pPart;
    cudaGetSymbolAddress(&pM, g_M);
    cudaGetSymbolAddress(&pH, g_H);
    cudaGetSymbolAddress(&pDeg, g_deg);
    cudaGetSymbolAddress(&pRow, g_rowptr);
    cudaGetSymbolAddress(&pCur, g_cursor);
    cudaGetSymbolAddress(&pSS, g_ssrc);
    cudaGetSymbolAddress(&pPart, g_partials);
    float* M = (float*)pM;
    float* H = (float*)pH;
    int *deg = (int*)pDeg, *rowptr = (int*)pRow, *cursor = (int*)pCur;
    int *ssrc = (int*)pSS, *partials = (int*)pPart;

    cudaFuncSetAttribute(gemm_norm_kernel,
                         cudaFuncAttributeMaxDynamicSharedMemorySize,
                         GEMM_SMEM_BYTES);

    const int gemm_grid   = (N_NODES + BM - 1) / BM;           // 1563
    const int edge_grid   = (N_EDGES + 255) / 256;             // 2344
    const int node_grid   = (N_NODES + 255) / 256;             // 391
    const int gather_grid = (N_NODES + 7) / 8;                 // 12500

    // ---- CSR build (graph static across both layers) ----
    cudaMemsetAsync(deg, 0, N_NODES * sizeof(int));
    hist_kernel<<<edge_grid, 256>>>(dst, deg);
    scan_block_kernel<<<NBLK, 256>>>(deg, rowptr, partials);
    scan_partials_kernel<<<1, 128>>>(partials);
    scan_add_kernel<<<node_grid, 256>>>(rowptr, partials, cursor);
    permute_kernel<<<edge_grid, 256>>>(src, dst, cursor, ssrc);

    // ---- Layer 1 ----
    gemm_norm_kernel<<<gemm_grid, 256, GEMM_SMEM_BYTES>>>(embed, node_id, W1, norm, M);
    gather_kernel<<<gather_grid, 256>>>(M, rowptr, deg, ssrc, norm, b1, H);

    // ---- Layer 2 ----
    gemm_norm_kernel<<<gemm_grid, 256, GEMM_SMEM_BYTES>>>(H, nullptr, W2, norm, M);
    gather_kernel<<<gather_grid, 256>>>(M, rowptr, deg, ssrc, norm, b2, out);
}